// round 12
// baseline (speedup 1.0000x reference)
#include <cuda_runtime.h>
#include <cuda_bf16.h>
#include <stdint.h>

typedef __nv_bfloat16  bf16;
typedef __nv_bfloat162 bf162;

#define BATCH 4
#define SEQ   2048
#define DM    1024
#define NH    16
#define HD    64
#define ROWS  8192
#define QC    3072
/* 0.125 * log2(e) : softmax computed in base-2 domain */
#define KSCL  0.1803368801111204f

/* ---------------- scratch (__device__ globals) --------------------- */
__device__ bf16 g_xh[(size_t)ROWS * DM];
__device__ bf16 g_xl[(size_t)ROWS * DM];
__device__ bf16 g_wqh[(size_t)QC * DM];
__device__ bf16 g_wql[(size_t)QC * DM];
__device__ bf16 g_woh[(size_t)DM * DM];
__device__ bf16 g_wol[(size_t)DM * DM];
__device__ bf16 g_qkvh[(size_t)ROWS * QC];
__device__ bf16 g_qkvl[(size_t)ROWS * QC];
__device__ bf16 g_ah[(size_t)ROWS * DM];
__device__ bf16 g_al[(size_t)ROWS * DM];

/* ---------------- helpers ------------------------------------------ */
__device__ __forceinline__ uint32_t s2u(const void* p) {
    uint32_t a;
    asm("{ .reg .u64 t; cvta.to.shared.u64 t, %1; cvt.u32.u64 %0, t; }"
        : "=r"(a) : "l"(p));
    return a;
}
__device__ __forceinline__ void ldsm4(uint32_t* d, uint32_t a) {
    asm volatile("ldmatrix.sync.aligned.m8n8.x4.shared.b16 {%0,%1,%2,%3}, [%4];"
        : "=r"(d[0]), "=r"(d[1]), "=r"(d[2]), "=r"(d[3]) : "r"(a));
}
__device__ __forceinline__ void ldsm4t(uint32_t* d, uint32_t a) {
    asm volatile("ldmatrix.sync.aligned.m8n8.x4.trans.shared.b16 {%0,%1,%2,%3}, [%4];"
        : "=r"(d[0]), "=r"(d[1]), "=r"(d[2]), "=r"(d[3]) : "r"(a));
}
__device__ __forceinline__ void mmabf(float* c, const uint32_t* a,
                                      uint32_t b0, uint32_t b1) {
    asm volatile("mma.sync.aligned.m16n8k16.row.col.f32.bf16.bf16.f32 "
        "{%0,%1,%2,%3}, {%4,%5,%6,%7}, {%8,%9}, {%0,%1,%2,%3};"
        : "+f"(c[0]), "+f"(c[1]), "+f"(c[2]), "+f"(c[3])
        : "r"(a[0]), "r"(a[1]), "r"(a[2]), "r"(a[3]), "r"(b0), "r"(b1));
}
#define CP16(s, g) \
    asm volatile("cp.async.cg.shared.global [%0], [%1], 16;" :: "r"(s), "l"(g))
#define CPCOMMIT() asm volatile("cp.async.commit_group;" ::: "memory")
#define CPWAIT(n)  asm volatile("cp.async.wait_group %0;" :: "n"(n) : "memory")

/* exp2 on the FMA pipe (deg-5 poly around 0, |f|<=0.5, rel err ~2e-6) */
__device__ __forceinline__ float exp2p(float x) {
    x = fmaxf(x, -100.f);
    int i = __float2int_rn(x);
    float f = x - (float)i;
    float p = fmaf(1.3333558146e-3f, f, 9.6181291076e-3f);
    p = fmaf(p, f, 5.5504108664e-2f);
    p = fmaf(p, f, 2.4022650696e-1f);
    p = fmaf(p, f, 6.9314718056e-1f);
    p = fmaf(p, f, 1.0f);
    return p * __int_as_float((i + 127) << 23);
}
/* split (v0,v1) fp32 -> bf16x2 hi (round-nearest) + bf16x2 residual */
__device__ __forceinline__ void split2(float v0, float v1,
                                       uint32_t& hi, uint32_t& lo) {
    bf16 h0 = __float2bfloat16(v0), h1 = __float2bfloat16(v1);
    bf162 H; H.x = h0; H.y = h1;
    bf162 L;
    L.x = __float2bfloat16(v0 - __bfloat162float(h0));
    L.y = __float2bfloat16(v1 - __bfloat162float(h1));
    hi = *(uint32_t*)&H; lo = *(uint32_t*)&L;
}

/* ---------------- fp32 -> bf16 hi/lo split kernels ------------------ */
__global__ __launch_bounds__(256) void split_kernel(
    const float* __restrict__ in, bf16* __restrict__ hi,
    bf16* __restrict__ lo, int n4)
{
    int i = blockIdx.x * 256 + threadIdx.x;
    if (i >= n4) return;
    float4 v = ((const float4*)in)[i];
    uint32_t h0, l0, h1, l1;
    split2(v.x, v.y, h0, l0);
    split2(v.z, v.w, h1, l1);
    ((uint32_t*)hi)[2 * i] = h0; ((uint32_t*)hi)[2 * i + 1] = h1;
    ((uint32_t*)lo)[2 * i] = l0; ((uint32_t*)lo)[2 * i + 1] = l1;
}

/* w [1024, Ncols] fp32 -> wT hi/lo [Ncols, 1024] bf16 (K contiguous) */
__global__ __launch_bounds__(256) void transpose_split_kernel(
    const float* __restrict__ w, bf16* __restrict__ th,
    bf16* __restrict__ tl, int Ncols)
{
    __shared__ float t[32][33];
    int n0 = blockIdx.x * 32, k0 = blockIdx.y * 32;
    int tx = threadIdx.x, ty = threadIdx.y;   /* block (32,8) */
#pragma unroll
    for (int i = 0; i < 4; i++)
        t[ty + 8 * i][tx] = w[(size_t)(k0 + ty + 8 * i) * Ncols + n0 + tx];
    __syncthreads();
#pragma unroll
    for (int i = 0; i < 4; i++) {
        float v = t[tx][ty + 8 * i];
        bf16 h = __float2bfloat16(v);
        size_t o = (size_t)(n0 + ty + 8 * i) * DM + k0 + tx;
        th[o] = h;
        tl[o] = __float2bfloat16(v - __bfloat162float(h));
    }
}

/* ------------------------------------------------------------------ */
/* GEMM v3: C[M,N] = A[M,K] * B[N,K]^T + bias, 3-term bf16 split.      */
/* Block 128x128, warp tile 64x32 (8 warps 2x4), BK=32, 3-stage        */
/* cp.async pipeline, __launch_bounds__(256,2) -> 2 CTAs/SM.           */
/* ------------------------------------------------------------------ */
#define GSTG  32768                     /* bytes per stage */
#define GEMM_SMEM (3 * GSTG)            /* 96 KB */

template<int SPLIT_OUT>
__global__ __launch_bounds__(256, 2) void gemm_mma_kernel(
    const bf16* __restrict__ Ah, const bf16* __restrict__ Al,
    const bf16* __restrict__ Bh, const bf16* __restrict__ Bl,
    const float* __restrict__ bias, float* __restrict__ Cf,
    bf16* __restrict__ Ch, bf16* __restrict__ Cl, int N)
{
    extern __shared__ __align__(1024) char sm[];
    const uint32_t sb = s2u(sm);
    const int tid = threadIdx.x, w = tid >> 5, lane = tid & 31;
    const int wm = w >> 2, wn = w & 3;      /* 2 x 4 warp grid */
    const int m0 = blockIdx.y << 7, n0 = blockIdx.x << 7;

    const int lr  = lane & 15;                       /* A-type ld row  */
    const int lg  = lane >> 4;                       /* A-type granule */
    const int brr = (lane & 7) + ((lane & 16) >> 1); /* B-type ld row  */
    const int bg  = (lane >> 3) & 1;                 /* B-type granule */
    const int g4  = lane >> 2, l4 = lane & 3;

    float c[4][4][4];                        /* 64 accumulator regs */
#pragma unroll
    for (int i = 0; i < 4; i++)
#pragma unroll
        for (int j = 0; j < 4; j++)
#pragma unroll
            for (int e = 0; e < 4; e++) c[i][j][e] = 0.f;

    /* cp.async one stage: Ah/Al/Bh/Bl 128x32 each, swizzled 64B rows */
    auto issue = [&](int stg, int k0) {
        uint32_t base = sb + stg * GSTG;
#pragma unroll
        for (int j = 0; j < 2; j++) {
            int idx = tid + j * 256, r = idx >> 2, g = idx & 3;
            uint32_t off = r * 64 + ((g ^ (r & 3)) << 4);
            size_t ga = (size_t)(m0 + r) * DM + k0 + g * 8;
            size_t gb = (size_t)(n0 + r) * DM + k0 + g * 8;
            CP16(base + off,          Ah + ga);
            CP16(base + 8192  + off,  Al + ga);
            CP16(base + 16384 + off,  Bh + gb);
            CP16(base + 24576 + off,  Bl + gb);
        }
        CPCOMMIT();
    };

    issue(0, 0); issue(1, 32); issue(2, 64);

#pragma unroll 1
    for (int s = 0; s < 32; s++) {
        CPWAIT(2);
        __syncthreads();
        uint32_t base = sb + (s % 3) * GSTG;
#pragma unroll
        for (int ks = 0; ks < 2; ks++) {
            uint32_t bh[2][4], bl[2][4];
#pragma unroll
            for (int jp = 0; jp < 2; jp++) {
                int rb = wn * 32 + jp * 16 + brr;
                uint32_t offB = rb * 64 + (((2 * ks + bg) ^ (rb & 3)) << 4);
                ldsm4(bh[jp], base + 16384 + offB);
                ldsm4(bl[jp], base + 24576 + offB);
            }
#pragma unroll
            for (int im = 0; im < 4; im++) {
                int ar = wm * 64 + im * 16 + lr;
                uint32_t offA = ar * 64 + (((2 * ks + lg) ^ (ar & 3)) << 4);
                uint32_t ah[4], al[4];
                ldsm4(ah, base + offA);
                ldsm4(al, base + 8192 + offA);
#pragma unroll
                for (int jp = 0; jp < 2; jp++) {
                    mmabf(c[im][2 * jp],     ah, bh[jp][0], bh[jp][1]);
                    mmabf(c[im][2 * jp + 1], ah, bh[jp][2], bh[jp][3]);
                    mmabf(c[im][2 * jp],     ah, bl[jp][0], bl[jp][1]);
                    mmabf(c[im][2 * jp + 1], ah, bl[jp][2], bl[jp][3]);
                    mmabf(c[im][2 * jp],     al, bh[jp][0], bh[jp][1]);
                    mmabf(c[im][2 * jp + 1], al, bh[jp][2], bh[jp][3]);
                }
            }
        }
        __syncthreads();
        if (s + 3 < 32) issue(s % 3, (s + 3) * 32);
    }

    /* epilogue */
#pragma unroll
    for (int im = 0; im < 4; im++) {
#pragma unroll
        for (int jn = 0; jn < 4; jn++) {
            int row = m0 + wm * 64 + im * 16 + g4;
            int col = n0 + wn * 32 + jn * 8 + l4 * 2;
            float2 bb = *(const float2*)(bias + col);
            float v0 = c[im][jn][0] + bb.x, v1 = c[im][jn][1] + bb.y;
            float v2 = c[im][jn][2] + bb.x, v3 = c[im][jn][3] + bb.y;
            if (SPLIT_OUT) {
                uint32_t h, l;
                split2(v0, v1, h, l);
                *(uint32_t*)(Ch + (size_t)row * N + col) = h;
                *(uint32_t*)(Cl + (size_t)row * N + col) = l;
                split2(v2, v3, h, l);
                *(uint32_t*)(Ch + (size_t)(row + 8) * N + col) = h;
                *(uint32_t*)(Cl + (size_t)(row + 8) * N + col) = l;
            } else {
                *(float2*)(Cf + (size_t)row * N + col)       = make_float2(v0, v1);
                *(float2*)(Cf + (size_t)(row + 8) * N + col) = make_float2(v2, v3);
            }
        }
    }
}

/* ------------------------------------------------------------------ */
/* Flash attention v2: BM=128, BN=64, 8 warps x 16 rows.               */
/* Smem 96 KB -> 2 CTAs/SM. S: 3-term split; P: 2-term split;          */
/* KV double-buffered via cp.async (32 KB/stage).                      */
/* ------------------------------------------------------------------ */
#define KVSTG 32768                      /* Kh,Kl,Vh,Vl: 64x64 x 8KB */
#define FLASH_SMEM (32768 + 2 * KVSTG)   /* 96 KB */

__global__ __launch_bounds__(256, 2) void flash_mma_kernel(
    const bf16* __restrict__ qh, const bf16* __restrict__ ql,
    bf16* __restrict__ oh, bf16* __restrict__ ol)
{
    extern __shared__ __align__(1024) char sm[];
    const uint32_t sQh = s2u(sm);
    const uint32_t sQl = sQh + 16384;
    const int tid = threadIdx.x, w = tid >> 5, lane = tid & 31;
    const int q0 = blockIdx.x << 7;
    const int b  = blockIdx.y >> 4, h = blockIdx.y & 15;
    const size_t rbase = (size_t)b * SEQ;
    const int qoff = h * HD, koff = DM + h * HD, voff = 2 * DM + h * HD;

    const int lr  = lane & 15;
    const int lg  = lane >> 4;
    const int brr = (lane & 7) + ((lane & 16) >> 1);
    const int bg  = (lane >> 3) & 1;
    const int g4  = lane >> 2, l4 = lane & 3;
    const int qrow = w * 16 + lr;

    /* cp.async one KV stage (Kh,Kl,Vh,Vl: 64x64 each, 128B rows) */
    auto kvload = [&](int stg, int kt) {
        uint32_t base = sQh + 32768 + stg * KVSTG;
#pragma unroll
        for (int j = 0; j < 2; j++) {
            int idx = tid + j * 256, rr = idx >> 3, g = idx & 7;
            size_t go = (rbase + kt + rr) * QC + g * 8;
            uint32_t off = rr * 128 + ((g ^ (rr & 7)) << 4);
            CP16(base + off,          qh + go + koff);
            CP16(base + 8192  + off,  ql + go + koff);
            CP16(base + 16384 + off,  qh + go + voff);
            CP16(base + 24576 + off,  ql + go + voff);
        }
        CPCOMMIT();
    };

    /* load Q tiles (hi & lo): 128x64 */
#pragma unroll
    for (int it = 0; it < 4; it++) {
        int idx = tid + it * 256, rr = idx >> 3, g = idx & 7;
        size_t go = (rbase + q0 + rr) * QC + qoff + g * 8;
        int so = rr * 128 + ((g ^ (rr & 7)) << 4);
        *(uint4*)(sm + so)         = *(const uint4*)(qh + go);
        *(uint4*)(sm + 16384 + so) = *(const uint4*)(ql + go);
    }
    kvload(0, 0);
    kvload(1, 64);

    float o[8][4];
#pragma unroll
    for (int j = 0; j < 8; j++)
#pragma unroll
        for (int e = 0; e < 4; e++) o[j][e] = 0.f;
    float m0 = -1e30f, m1 = -1e30f, l0 = 0.f, l1 = 0.f;

#pragma unroll 1
    for (int it = 0; it < SEQ / 64; it++) {
        CPWAIT(1);
        __syncthreads();
        const uint32_t sKh = sQh + 32768 + (it & 1) * KVSTG;
        const uint32_t sKl = sKh + 8192, sVh = sKh + 16384, sVl = sKh + 24576;

        /* ---- S = Q K^T (3 products), K-rows in pairs: 4-acc rotation */
        float s[8][4];
#pragma unroll
        for (int j = 0; j < 8; j++)
#pragma unroll
            for (int e = 0; e < 4; e++) s[j][e] = 0.f;

#pragma unroll
        for (int ks = 0; ks < 4; ks++) {
            uint32_t ah[4], al[4];
            int offA = qrow * 128 + (((2 * ks + lg) ^ (qrow & 7)) << 4);
            ldsm4(ah, sQh + offA);
            ldsm4(al, sQl + offA);
#pragma unroll
            for (int jpp = 0; jpp < 2; jpp++) {
                int rb0 = (2 * jpp) * 16 + brr;
                int rb1 = (2 * jpp + 1) * 16 + brr;
                int offB0 = rb0 * 128 + (((2 * ks + bg) ^ (rb0 & 7)) << 4);
                int offB1 = rb1 * 128 + (((2 * ks + bg) ^ (rb1 & 7)) << 4);
                uint32_t bhA[4], blA[4], bhB[4], blB[4];
                ldsm4(bhA, sKh + offB0);
                ldsm4(blA, sKl + offB0);
                ldsm4(bhB, sKh + offB1);
                ldsm4(blB, sKl + offB1);
                float* s0 = s[4 * jpp];     float* s1 = s[4 * jpp + 1];
                float* s2 = s[4 * jpp + 2]; float* s3 = s[4 * jpp + 3];
                mmabf(s0, ah, bhA[0], bhA[1]);
                mmabf(s1, ah, bhA[2], bhA[3]);
                mmabf(s2, ah, bhB[0], bhB[1]);
                mmabf(s3, ah, bhB[2], bhB[3]);
                mmabf(s0, ah, blA[0], blA[1]);
                mmabf(s1, ah, blA[2], blA[3]);
                mmabf(s2, ah, blB[0], blB[1]);
                mmabf(s3, ah, blB[2], blB[3]);
                mmabf(s0, al, bhA[0], bhA[1]);
                mmabf(s1, al, bhA[2], bhA[3]);
                mmabf(s2, al, bhB[0], bhB[1]);
                mmabf(s3, al, bhB[2], bhB[3]);
            }
        }

        /* ---- online softmax (base-2 domain, FMA-pipe exp2) ---- */
        float mx0 = -1e30f, mx1 = -1e30f;
#pragma unroll
        for (int j = 0; j < 8; j++) {
            mx0 = fmaxf(mx0, fmaxf(s[j][0], s[j][1]));
            mx1 = fmaxf(mx1, fmaxf(s[j][2], s[j][3]));
        }
        mx0 *= KSCL; mx1 *= KSCL;
#pragma unroll
        for (int ofs = 1; ofs <= 2; ofs <<= 1) {
            mx0 = fmaxf(mx0, __shfl_xor_sync(0xffffffffu, mx0, ofs));
            mx1 = fmaxf(mx1, __shfl_xor_sync(0xffffffffu, mx1, ofs));
        }
        float nm0 = fmaxf(m0, mx0), nm1 = fmaxf(m1, mx1);
        float a0 = exp2p(m0 - nm0), a1 = exp2p(m1 - nm1);
        m0 = nm0; m1 = nm1;

        float rs0 = 0.f, rs1 = 0.f;
#pragma unroll
        for (int j = 0; j < 8; j++) {
            s[j][0] = exp2p(fmaf(s[j][0], KSCL, -m0));
            s[j][1] = exp2p(fmaf(s[j][1], KSCL, -m0));
            s[j][2] = exp2p(fmaf(s[j][2], KSCL, -m1));
            s[j][3] = exp2p(fmaf(s[j][3], KSCL, -m1));
            rs0 += s[j][0] + s[j][1];
            rs1 += s[j][2] + s[j][3];
        }
#pragma unroll
        for (int ofs = 1; ofs <= 2; ofs <<= 1) {
            rs0 += __shfl_xor_sync(0xffffffffu, rs0, ofs);
            rs1 += __shfl_xor_sync(0xffffffffu, rs1, ofs);
        }
        l0 = l0 * a0 + rs0;
        l1 = l1 * a1 + rs1;
#pragma unroll
        for (int j = 0; j < 8; j++) {
            o[j][0] *= a0; o[j][1] *= a0;
            o[j][2] *= a1; o[j][3] *= a1;
        }

        /* ---- O += Ph*Vh + Pl*Vh + Ph*Vl, V-cols in pairs: 4-acc ---- */
#pragma unroll
        for (int ks = 0; ks < 4; ks++) {
            uint32_t pah[4], pal[4];
            split2(s[2 * ks][0],     s[2 * ks][1],     pah[0], pal[0]);
            split2(s[2 * ks][2],     s[2 * ks][3],     pah[1], pal[1]);
            split2(s[2 * ks + 1][0], s[2 * ks + 1][1], pah[2], pal[2]);
            split2(s[2 * ks + 1][2], s[2 * ks + 1][3], pah[3], pal[3]);
            int vr = ks * 16 + lr;
#pragma unroll
            for (int jpp = 0; jpp < 2; jpp++) {
                int offV0 = vr * 128 + (((4 * jpp + lg)     ^ (vr & 7)) << 4);
                int offV1 = vr * 128 + (((4 * jpp + 2 + lg) ^ (vr & 7)) << 4);
                uint32_t vhA[4], vlA[4], vhB[4], vlB[4];
                ldsm4t(vhA, sVh + offV0);
                ldsm4t(vlA, sVl + offV0);
                ldsm4t(vhB, sVh + offV1);
                ldsm4t(vlB, sVl + offV1);
                float* o0 = o[4 * jpp];     float* o1 = o[4 * jpp + 1];
                float* o2 = o[4 * jpp + 2]; float* o3 = o[4 * jpp + 3];
                mmabf(o0, pah, vhA[0], vhA[1]);
                mmabf(o1, pah, vhA[2], vhA[3]);
                mmabf(o2, pah, vhB[0], vhB[1]);
                mmabf(o3, pah, vhB[2], vhB[3]);
                mmabf(o0, pal, vhA[0], vhA[1]);
                mmabf(o1, pal, vhA[2], vhA[3]);
                mmabf(o2, pal, vhB[0], vhB[1]);
                mmabf(o3, pal, vhB[2], vhB[3]);
                mmabf(o0, pah, vlA[0], vlA[1]);
                mmabf(o1, pah, vlA[2], vlA[3]);
                mmabf(o2, pah, vlB[0], vlB[1]);
                mmabf(o3, pah, vlB[2], vlB[3]);
            }
        }
        __syncthreads();
        if (it + 2 < SEQ / 64) kvload(it & 1, (it + 2) * 64);
    }

    /* epilogue: normalize and write bf16 hi/lo */
    float i0 = 1.f / l0, i1 = 1.f / l1;
    size_t r0 = rbase + q0 + w * 16 + g4;
#pragma unroll
    for (int jn = 0; jn < 8; jn++) {
        int col = qoff + jn * 8 + l4 * 2;
        uint32_t hh, ll;
        split2(o[jn][0] * i0, o[jn][1] * i0, hh, ll);
        *(uint32_t*)(oh + r0 * DM + col) = hh;
        *(uint32_t*)(ol + r0 * DM + col) = ll;
        split2(o[jn][2] * i1, o[jn][3] * i1, hh, ll);
        *(uint32_t*)(oh + (r0 + 8) * DM + col) = hh;
        *(uint32_t*)(ol + (r0 + 8) * DM + col) = ll;
    }
}

/* ------------------------------------------------------------------ */
extern "C" void kernel_launch(void* const* d_in, const int* in_sizes, int n_in,
                              void* d_out, int out_size)
{
    (void)in_sizes; (void)n_in; (void)out_size;
    const float* x     = (const float*)d_in[0];
    const float* w_qkv = (const float*)d_in[1];
    const float* b_qkv = (const float*)d_in[2];
    const float* w_out = (const float*)d_in[3];
    const float* b_out = (const float*)d_in[4];
    float* out = (float*)d_out;

    bf16 *xh, *xl, *wqh, *wql, *woh, *wol, *qkvh, *qkvl, *ah, *al;
    cudaGetSymbolAddress((void**)&xh,   g_xh);
    cudaGetSymbolAddress((void**)&xl,   g_xl);
    cudaGetSymbolAddress((void**)&wqh,  g_wqh);
    cudaGetSymbolAddress((void**)&wql,  g_wql);
    cudaGetSymbolAddress((void**)&woh,  g_woh);
    cudaGetSymbolAddress((void**)&wol,  g_wol);
    cudaGetSymbolAddress((void**)&qkvh, g_qkvh);
    cudaGetSymbolAddress((void**)&qkvl, g_qkvl);
    cudaGetSymbolAddress((void**)&ah,   g_ah);
    cudaGetSymbolAddress((void**)&al,   g_al);

    cudaFuncSetAttribute(flash_mma_kernel,
                         cudaFuncAttributeMaxDynamicSharedMemorySize, FLASH_SMEM);
    cudaFuncSetAttribute(gemm_mma_kernel<1>,
                         cudaFuncAttributeMaxDynamicSharedMemorySize, GEMM_SMEM);
    cudaFuncSetAttribute(gemm_mma_kernel<0>,
                         cudaFuncAttributeMaxDynamicSharedMemorySize, GEMM_SMEM);

    /* 0) precision-split inputs + transposed weights */
    split_kernel<<<(ROWS * DM / 4 + 255) / 256, 256>>>(x, xh, xl, ROWS * DM / 4);
    transpose_split_kernel<<<dim3(QC / 32, DM / 32), dim3(32, 8)>>>(w_qkv, wqh, wql, QC);
    transpose_split_kernel<<<dim3(DM / 32, DM / 32), dim3(32, 8)>>>(w_out, woh, wol, DM);

    /* 1) QKV projection (writes bf16 hi/lo directly) */
    gemm_mma_kernel<1><<<dim3(QC / 128, ROWS / 128), 256, GEMM_SMEM>>>(
        xh, xl, wqh, wql, b_qkv, nullptr, qkvh, qkvl, QC);

    /* 2) flash attention (writes bf16 hi/lo) */
    flash_mma_kernel<<<dim3(SEQ / 128, BATCH * NH), 256, FLASH_SMEM>>>(
        qkvh, qkvl, ah, al);

    /* 3) output projection (writes fp32 final) */
    gemm_mma_kernel<0><<<dim3(DM / 128, ROWS / 128), 256, GEMM_SMEM>>>(
        ah, al, woh, wol, b_out, out, nullptr, nullptr, DM);
}